// round 13
// baseline (speedup 1.0000x reference)
#include <cuda_runtime.h>
#include <cuda_bf16.h>
#include <math.h>

#define BATCH 16
#define CH 512
#define HWN 4096
#define NHEAD 8
#define HD 64
#define BH (BATCH * NHEAD)  // 128

__device__ float g_K[(size_t)BATCH * CH * HWN];
__device__ float g_V[(size_t)BATCH * CH * HWN];
__device__ float g_ctx[BH * HD * HD];          // [bh][d][e]
__device__ float g_M[(size_t)BATCH * CH * CH]; // [b][ch][c]
__device__ float g_G[(size_t)BATCH * CH * CH]; // [b][o][c]
__device__ float g_s[CH];
__device__ float g_s2[CH];
__device__ float g_mean[CH];
__device__ float g_rstd[CH];

typedef unsigned long long u64;

// packed f32x2 helpers (FFMA2 path: only reachable via PTX, per SASS_QUICKREF)
#define FFMA2(d, a, b) \
  asm("fma.rn.f32x2 %0, %1, %2, %0;" : "+l"(d) : "l"(a), "l"(b))
#define PACK2(out, lo, hi) \
  asm("mov.b64 %0, {%1, %2};" : "=l"(out) : "f"(lo), "f"(hi))
#define UNPACK2(lo, hi, in) \
  asm("mov.b64 {%0, %1}, %2;" : "=f"(lo), "=f"(hi) : "l"(in))

// ---------------------------------------------------------------------------
// K0: zero ctx accumulator + BN partial sums.
// ---------------------------------------------------------------------------
__global__ __launch_bounds__(256) void k_zero() {
  const int i = blockIdx.x * 256 + threadIdx.x;
  if (i < BH * HD * HD) g_ctx[i] = 0.f;
  if (i < CH) { g_s[i] = 0.f; g_s2[i] = 0.f; }
}

// ---------------------------------------------------------------------------
// K1: K/V projections, softmax fused into K epilogue. f32x2 inner loop.
// Kc=8, double-buffered stages, one barrier per chunk.
// grid = (32, 8, 16): blockIdx.y -> (which = y>>2, m-tile = y&3)
// ---------------------------------------------------------------------------
__global__ __launch_bounds__(256) void k_gemm_kv(
    const float* __restrict__ x, const float* __restrict__ Wk,
    const float* __restrict__ Wv) {
  const int b = blockIdx.z;
  const int n0 = blockIdx.x * 128;
  const int which = blockIdx.y >> 2;   // 0=K, 1=V
  const int m0 = (blockIdx.y & 3) * 128;
  const float* __restrict__ W = (which == 0) ? Wk : Wv;
  float* Out = (which == 0) ? g_K : g_V;
  const float* __restrict__ Bp = x + (size_t)b * CH * HWN;

  __shared__ float sbuf[4096];

  const int tid = threadIdx.x;
  const int tx = tid & 15, ty = tid >> 4;
  const int arow = tid >> 1, acol = (tid & 1) << 2;
  const int brow = tid >> 5, bcol = (tid & 31) << 2;

  u64 acc2[8][4];
  {
    u64 z;
    PACK2(z, 0.f, 0.f);
#pragma unroll
    for (int i = 0; i < 8; i++)
#pragma unroll
      for (int j = 0; j < 4; j++) acc2[i][j] = z;
  }

  const float* Arow = W + (size_t)(m0 + arow) * CH;

  float4 av = *(const float4*)&Arow[acol];
  float4 bv = *(const float4*)&Bp[(size_t)brow * HWN + n0 + bcol];
  {
    float* As = sbuf;
    float* Bs = sbuf + 1024;
    As[(acol + 0) * 128 + arow] = av.x;
    As[(acol + 1) * 128 + arow] = av.y;
    As[(acol + 2) * 128 + arow] = av.z;
    As[(acol + 3) * 128 + arow] = av.w;
    *(float4*)&Bs[brow * 128 + bcol] = bv;
  }
  __syncthreads();

#pragma unroll 1
  for (int c = 0; c < 64; c++) {
    const int cur = c & 1;
    const bool more = (c + 1) < 64;
    if (more) {
      const int kn = (c + 1) * 8;
      av = *(const float4*)&Arow[kn + acol];
      bv = *(const float4*)&Bp[(size_t)(kn + brow) * HWN + n0 + bcol];
    }
    const float* As = sbuf + cur * 2048;
    const float* Bs = As + 1024;
#pragma unroll
    for (int kk = 0; kk < 8; kk++) {
      float a[8];
      *(float4*)&a[0] = *(const float4*)&As[kk * 128 + ty * 8];
      *(float4*)&a[4] = *(const float4*)&As[kk * 128 + ty * 8 + 4];
      u64 bb2[4];
      *(ulonglong2*)&bb2[0] = *(const ulonglong2*)&Bs[kk * 128 + tx * 8];
      *(ulonglong2*)&bb2[2] = *(const ulonglong2*)&Bs[kk * 128 + tx * 8 + 4];
#pragma unroll
      for (int i = 0; i < 8; i++) {
        u64 aa;
        PACK2(aa, a[i], a[i]);
#pragma unroll
        for (int j = 0; j < 4; j++) FFMA2(acc2[i][j], aa, bb2[j]);
      }
    }
    if (more) {
      float* An = sbuf + (cur ^ 1) * 2048;
      float* Bn = An + 1024;
      An[(acol + 0) * 128 + arow] = av.x;
      An[(acol + 1) * 128 + arow] = av.y;
      An[(acol + 2) * 128 + arow] = av.z;
      An[(acol + 3) * 128 + arow] = av.w;
      *(float4*)&Bn[brow * 128 + bcol] = bv;
    }
    __syncthreads();
  }

  float acc[8][8];
#pragma unroll
  for (int i = 0; i < 8; i++)
#pragma unroll
    for (int j = 0; j < 4; j++)
      UNPACK2(acc[i][2 * j], acc[i][2 * j + 1], acc2[i][j]);

  if (which == 0) {
    // softmax over d (64 rows/head); rows 0-63 = head A (ty 0-7), 64-127 = B.
    float* red = sbuf;
    const int tb = (ty < 8) ? 0 : 8;
    const int rbase = (ty * 16 + tx) * 8;
    float loc[8];
#pragma unroll
    for (int j = 0; j < 8; j++) {
      float m = acc[0][j];
#pragma unroll
      for (int i = 1; i < 8; i++) m = fmaxf(m, acc[i][j]);
      loc[j] = m;
    }
    *(float4*)&red[rbase] = *(float4*)&loc[0];
    *(float4*)&red[rbase + 4] = *(float4*)&loc[4];
    __syncthreads();
    float gm[8];
#pragma unroll
    for (int j = 0; j < 8; j++) gm[j] = -3.4e38f;
#pragma unroll
    for (int t = 0; t < 8; t++) {
      const int rb = ((tb + t) * 16 + tx) * 8;
      float4 r0 = *(float4*)&red[rb];
      float4 r1 = *(float4*)&red[rb + 4];
      gm[0] = fmaxf(gm[0], r0.x); gm[1] = fmaxf(gm[1], r0.y);
      gm[2] = fmaxf(gm[2], r0.z); gm[3] = fmaxf(gm[3], r0.w);
      gm[4] = fmaxf(gm[4], r1.x); gm[5] = fmaxf(gm[5], r1.y);
      gm[6] = fmaxf(gm[6], r1.z); gm[7] = fmaxf(gm[7], r1.w);
    }
#pragma unroll
    for (int j = 0; j < 8; j++) loc[j] = 0.f;
#pragma unroll
    for (int i = 0; i < 8; i++)
#pragma unroll
      for (int j = 0; j < 8; j++) {
        acc[i][j] = expf(acc[i][j] - gm[j]);
        loc[j] += acc[i][j];
      }
    __syncthreads();
    *(float4*)&red[rbase] = *(float4*)&loc[0];
    *(float4*)&red[rbase + 4] = *(float4*)&loc[4];
    __syncthreads();
    float gs[8];
#pragma unroll
    for (int j = 0; j < 8; j++) gs[j] = 0.f;
#pragma unroll
    for (int t = 0; t < 8; t++) {
      const int rb = ((tb + t) * 16 + tx) * 8;
      float4 r0 = *(float4*)&red[rb];
      float4 r1 = *(float4*)&red[rb + 4];
      gs[0] += r0.x; gs[1] += r0.y; gs[2] += r0.z; gs[3] += r0.w;
      gs[4] += r1.x; gs[5] += r1.y; gs[6] += r1.z; gs[7] += r1.w;
    }
#pragma unroll
    for (int j = 0; j < 8; j++) gs[j] = 1.f / gs[j];
#pragma unroll
    for (int i = 0; i < 8; i++)
#pragma unroll
      for (int j = 0; j < 8; j++) acc[i][j] *= gs[j];
  }

  float* O = Out + ((size_t)b * CH + m0) * HWN + n0;
#pragma unroll
  for (int i = 0; i < 8; i++) {
    float* row = O + (size_t)(ty * 8 + i) * HWN + tx * 8;
    *(float4*)&row[0] = make_float4(acc[i][0], acc[i][1], acc[i][2], acc[i][3]);
    *(float4*)&row[4] = make_float4(acc[i][4], acc[i][5], acc[i][6], acc[i][7]);
  }
}

// ---------------------------------------------------------------------------
// K3: context[bh][d][e] = sum_p K[bh][d][p] * V[bh][e][p]. f32x2 inner loop.
// 64 threads, 8x8 microtile. grid = (8 splits, 128 bh).
// ---------------------------------------------------------------------------
__global__ __launch_bounds__(64) void k_context() {
  const int bh = blockIdx.y;
  const int p0 = blockIdx.x * 512;
  const float* __restrict__ krow =
      g_K + (size_t)bh * HD * HWN + (size_t)threadIdx.x * HWN + p0;
  const float* __restrict__ vrow =
      g_V + (size_t)bh * HD * HWN + (size_t)threadIdx.x * HWN + p0;
  __shared__ __align__(16) float As[16][68];
  __shared__ __align__(16) float Bs[16][68];
  const int tid = threadIdx.x;
  const int tx = tid & 7, ty = tid >> 3;

  u64 acc2[8][4];
  {
    u64 z;
    PACK2(z, 0.f, 0.f);
#pragma unroll
    for (int i = 0; i < 8; i++)
#pragma unroll
      for (int j = 0; j < 4; j++) acc2[i][j] = z;
  }

  float4 kr[4], vr[4];
#pragma unroll
  for (int j = 0; j < 4; j++) {
    kr[j] = *(const float4*)&krow[j * 4];
    vr[j] = *(const float4*)&vrow[j * 4];
  }

  for (int c = 0; c < 32; c++) {
#pragma unroll
    for (int j = 0; j < 4; j++) {
      As[j * 4 + 0][tid] = kr[j].x; As[j * 4 + 1][tid] = kr[j].y;
      As[j * 4 + 2][tid] = kr[j].z; As[j * 4 + 3][tid] = kr[j].w;
      Bs[j * 4 + 0][tid] = vr[j].x; Bs[j * 4 + 1][tid] = vr[j].y;
      Bs[j * 4 + 2][tid] = vr[j].z; Bs[j * 4 + 3][tid] = vr[j].w;
    }
    __syncthreads();
    if (c + 1 < 32) {
      const int pn = (c + 1) * 16;
#pragma unroll
      for (int j = 0; j < 4; j++) {
        kr[j] = *(const float4*)&krow[pn + j * 4];
        vr[j] = *(const float4*)&vrow[pn + j * 4];
      }
    }
#pragma unroll
    for (int kk = 0; kk < 16; kk++) {
      float a[8];
      *(float4*)&a[0] = *(const float4*)&As[kk][ty * 8];
      *(float4*)&a[4] = *(const float4*)&As[kk][ty * 8 + 4];
      u64 bb2[4];
      *(ulonglong2*)&bb2[0] = *(const ulonglong2*)&Bs[kk][tx * 8];
      *(ulonglong2*)&bb2[2] = *(const ulonglong2*)&Bs[kk][tx * 8 + 4];
#pragma unroll
      for (int i = 0; i < 8; i++) {
        u64 aa;
        PACK2(aa, a[i], a[i]);
#pragma unroll
        for (int j = 0; j < 4; j++) FFMA2(acc2[i][j], aa, bb2[j]);
      }
    }
    __syncthreads();
  }
  float* C = g_ctx + (size_t)bh * HD * HD;
#pragma unroll
  for (int i = 0; i < 8; i++)
#pragma unroll
    for (int j = 0; j < 4; j++) {
      float lo, hi;
      UNPACK2(lo, hi, acc2[i][j]);
      atomicAdd(&C[(ty * 8 + i) * HD + tx * 8 + 2 * j], lo);
      atomicAdd(&C[(ty * 8 + i) * HD + tx * 8 + 2 * j + 1], hi);
    }
}

// ---------------------------------------------------------------------------
// K4: M[b][h*64+e][c] = sum_d ctx[bh][d][e] * Wq[h*64+d][c]   (proven)
// ---------------------------------------------------------------------------
__global__ __launch_bounds__(256) void k_mk(const float* __restrict__ Wq) {
  const int bh = blockIdx.y;
  const int b = bh >> 3, h = bh & 7;
  const int c0 = blockIdx.x * 64;
  const int tid = threadIdx.x;

  __shared__ float cs[64][65];
  __shared__ float ws[64][65];
  const float* C = g_ctx + (size_t)bh * HD * HD;
  for (int i = tid; i < 1024; i += 256) {
    float4 v = ((const float4*)C)[i];
    const int d = i >> 4, e = (i & 15) * 4;
    cs[d][e + 0] = v.x; cs[d][e + 1] = v.y;
    cs[d][e + 2] = v.z; cs[d][e + 3] = v.w;
  }
  for (int i = tid; i < 1024; i += 256) {
    const int d = i >> 4, c = (i & 15) * 4;
    float4 v = *(const float4*)&Wq[(size_t)(h * 64 + d) * CH + c0 + c];
    ws[d][c + 0] = v.x; ws[d][c + 1] = v.y;
    ws[d][c + 2] = v.z; ws[d][c + 3] = v.w;
  }
  __syncthreads();

  const int tx = tid & 15, ty = tid >> 4;
  float acc[4][4];
#pragma unroll
  for (int i = 0; i < 4; i++)
#pragma unroll
    for (int j = 0; j < 4; j++) acc[i][j] = 0.f;

  for (int d = 0; d < 64; d++) {
    float a[4], w[4];
#pragma unroll
    for (int i = 0; i < 4; i++) a[i] = cs[d][ty * 4 + i];
#pragma unroll
    for (int j = 0; j < 4; j++) w[j] = ws[d][tx * 4 + j];
#pragma unroll
    for (int i = 0; i < 4; i++)
#pragma unroll
      for (int j = 0; j < 4; j++) acc[i][j] += a[i] * w[j];
  }
#pragma unroll
  for (int i = 0; i < 4; i++)
#pragma unroll
    for (int j = 0; j < 4; j++)
      g_M[((size_t)b * CH + h * 64 + ty * 4 + i) * CH + c0 + tx * 4 + j] =
          acc[i][j];
}

// ---------------------------------------------------------------------------
// K5: G[b][o][c] = sum_ch Wo[o][ch] * M[b][ch][c]   (proven, stride 512)
// ---------------------------------------------------------------------------
__global__ __launch_bounds__(256) void k_gk(const float* __restrict__ Wo) {
  const int b = blockIdx.z;
  const int n0 = blockIdx.x * 128;
  const int m0 = blockIdx.y * 128;
  const float* __restrict__ Bp = g_M + (size_t)b * CH * CH;

  __shared__ float As[8][128];
  __shared__ float Bs[8][128];
  const int tid = threadIdx.x;
  const int tx = tid & 15, ty = tid >> 4;
  const int arow = tid >> 1, acol = (tid & 1) << 2;
  const int brow = tid >> 5, bcol = (tid & 31) << 2;

  float acc[8][8];
#pragma unroll
  for (int i = 0; i < 8; i++)
#pragma unroll
    for (int j = 0; j < 8; j++) acc[i][j] = 0.f;

  for (int k0 = 0; k0 < CH; k0 += 8) {
    float4 av = *(const float4*)&Wo[(size_t)(m0 + arow) * CH + k0 + acol];
    As[acol + 0][arow] = av.x;
    As[acol + 1][arow] = av.y;
    As[acol + 2][arow] = av.z;
    As[acol + 3][arow] = av.w;
    *(float4*)&Bs[brow][bcol] =
        *(const float4*)&Bp[(size_t)(k0 + brow) * CH + n0 + bcol];
    __syncthreads();
#pragma unroll
    for (int kk = 0; kk < 8; kk++) {
      float a[8], bb[8];
      *(float4*)&a[0] = *(float4*)&As[kk][ty * 8];
      *(float4*)&a[4] = *(float4*)&As[kk][ty * 8 + 4];
      *(float4*)&bb[0] = *(float4*)&Bs[kk][tx * 8];
      *(float4*)&bb[4] = *(float4*)&Bs[kk][tx * 8 + 4];
#pragma unroll
      for (int i = 0; i < 8; i++)
#pragma unroll
        for (int j = 0; j < 8; j++) acc[i][j] += a[i] * bb[j];
    }
    __syncthreads();
  }
  float* O = g_G + ((size_t)b * CH + m0) * CH + n0;
#pragma unroll
  for (int i = 0; i < 8; i++) {
    float* row = O + (size_t)(ty * 8 + i) * CH + tx * 8;
    *(float4*)&row[0] = make_float4(acc[i][0], acc[i][1], acc[i][2], acc[i][3]);
    *(float4*)&row[4] = make_float4(acc[i][4], acc[i][5], acc[i][6], acc[i][7]);
  }
}

// ---------------------------------------------------------------------------
// K6: y = G_b @ x + x, BN stats fused. f32x2 inner loop.
// grid = (32, 4, 16).
// ---------------------------------------------------------------------------
__global__ __launch_bounds__(256) void k_final(const float* __restrict__ x,
                                               float* __restrict__ y) {
  const int b = blockIdx.z;
  const int n0 = blockIdx.x * 128;
  const int m0 = blockIdx.y * 128;
  const float* __restrict__ A = g_G + (size_t)b * CH * CH;
  const float* __restrict__ Bp = x + (size_t)b * CH * HWN;

  __shared__ float As[8][128];
  __shared__ float Bs[8][128];
  const int tid = threadIdx.x;
  const int tx = tid & 15, ty = tid >> 4;
  const int arow = tid >> 1, acol = (tid & 1) << 2;
  const int brow = tid >> 5, bcol = (tid & 31) << 2;

  u64 acc2[8][4];
  {
    u64 z;
    PACK2(z, 0.f, 0.f);
#pragma unroll
    for (int i = 0; i < 8; i++)
#pragma unroll
      for (int j = 0; j < 4; j++) acc2[i][j] = z;
  }

  float4 av = *(const float4*)&A[(size_t)(m0 + arow) * CH + acol];
  float4 bv = *(const float4*)&Bp[(size_t)brow * HWN + n0 + bcol];

  for (int k0 = 0; k0 < CH; k0 += 8) {
    As[acol + 0][arow] = av.x;
    As[acol + 1][arow] = av.y;
    As[acol + 2][arow] = av.z;
    As[acol + 3][arow] = av.w;
    *(float4*)&Bs[brow][bcol] = bv;
    __syncthreads();
    if (k0 + 8 < CH) {
      av = *(const float4*)&A[(size_t)(m0 + arow) * CH + k0 + 8 + acol];
      bv = *(const float4*)&Bp[(size_t)(k0 + 8 + brow) * HWN + n0 + bcol];
    }
#pragma unroll
    for (int kk = 0; kk < 8; kk++) {
      float a[8];
      *(float4*)&a[0] = *(float4*)&As[kk][ty * 8];
      *(float4*)&a[4] = *(float4*)&As[kk][ty * 8 + 4];
      u64 bb2[4];
      *(ulonglong2*)&bb2[0] = *(const ulonglong2*)&Bs[kk][tx * 8];
      *(ulonglong2*)&bb2[2] = *(const ulonglong2*)&Bs[kk][tx * 8 + 4];
#pragma unroll
      for (int i = 0; i < 8; i++) {
        u64 aa;
        PACK2(aa, a[i], a[i]);
#pragma unroll
        for (int j = 0; j < 4; j++) FFMA2(acc2[i][j], aa, bb2[j]);
      }
    }
    __syncthreads();
  }

  float acc[8][8];
#pragma unroll
  for (int i = 0; i < 8; i++)
#pragma unroll
    for (int j = 0; j < 4; j++)
      UNPACK2(acc[i][2 * j], acc[i][2 * j + 1], acc2[i][j]);

#pragma unroll
  for (int i = 0; i < 8; i++) {
    const size_t base = ((size_t)b * CH + m0 + ty * 8 + i) * HWN + n0 + tx * 8;
    float4 x0 = *(const float4*)&x[base];
    float4 x1 = *(const float4*)&x[base + 4];
    acc[i][0] += x0.x; acc[i][1] += x0.y; acc[i][2] += x0.z; acc[i][3] += x0.w;
    acc[i][4] += x1.x; acc[i][5] += x1.y; acc[i][6] += x1.z; acc[i][7] += x1.w;
    *(float4*)&y[base] = make_float4(acc[i][0], acc[i][1], acc[i][2], acc[i][3]);
    *(float4*)&y[base + 4] =
        make_float4(acc[i][4], acc[i][5], acc[i][6], acc[i][7]);
  }

#pragma unroll
  for (int i = 0; i < 8; i++) {
    float s = 0.f, s2 = 0.f;
#pragma unroll
    for (int j = 0; j < 8; j++) {
      s += acc[i][j];
      s2 += acc[i][j] * acc[i][j];
    }
#pragma unroll
    for (int d = 8; d > 0; d >>= 1) {
      s += __shfl_down_sync(0xffffffffu, s, d, 16);
      s2 += __shfl_down_sync(0xffffffffu, s2, d, 16);
    }
    if (tx == 0) {
      const int ch = m0 + ty * 8 + i;
      atomicAdd(&g_s[ch], s);
      atomicAdd(&g_s2[ch], s2);
    }
  }
}

// ---------------------------------------------------------------------------
// K7: finalize BN stats.  one block, 512 threads.
// ---------------------------------------------------------------------------
__global__ void k_bn_finalize() {
  const int c = threadIdx.x;
  const float inv_n = 1.f / (float)(BATCH * HWN);
  const float mean = g_s[c] * inv_n;
  const float var = g_s2[c] * inv_n - mean * mean;
  g_mean[c] = mean;
  g_rstd[c] = rsqrtf(var + 1e-5f);
}

// ---------------------------------------------------------------------------
// K8: normalize in place + affine.
// ---------------------------------------------------------------------------
__global__ __launch_bounds__(256) void k_bn_apply(float* __restrict__ y,
                                                  const float* __restrict__ gamma,
                                                  const float* __restrict__ beta) {
  const size_t i4 = (size_t)blockIdx.x * 256 + threadIdx.x;
  const int c = (int)((i4 >> 10) & (CH - 1));
  float4 v = ((const float4*)y)[i4];
  const float mu = g_mean[c];
  const float sc = g_rstd[c] * gamma[c];
  const float bt = beta[c];
  v.x = (v.x - mu) * sc + bt;
  v.y = (v.y - mu) * sc + bt;
  v.z = (v.z - mu) * sc + bt;
  v.w = (v.w - mu) * sc + bt;
  ((float4*)y)[i4] = v;
}

// ---------------------------------------------------------------------------
extern "C" void kernel_launch(void* const* d_in, const int* in_sizes, int n_in,
                              void* d_out, int out_size) {
  const float* x = (const float*)d_in[0];
  const float* Wq = (const float*)d_in[1];
  const float* Wk = (const float*)d_in[2];
  const float* Wv = (const float*)d_in[3];
  const float* Wo = (const float*)d_in[4];
  const float* gamma = (const float*)d_in[5];
  const float* beta = (const float*)d_in[6];
  float* y = (float*)d_out;

  k_zero<<<2048, 256>>>();
  k_gemm_kv<<<dim3(32, 8, 16), 256>>>(x, Wk, Wv);
  k_context<<<dim3(8, 128), 64>>>();
  k_mk<<<dim3(8, 128), 256>>>(Wq);
  k_gk<<<dim3(4, 4, 16), 256>>>(Wo);
  k_final<<<dim3(32, 4, 16), 256>>>(x, y);
  k_bn_finalize<<<1, 512>>>();
  k_bn_apply<<<32768, 256>>>(y, gamma, beta);
}

// round 14
// speedup vs baseline: 1.0467x; 1.0467x over previous
#include <cuda_runtime.h>
#include <cuda_bf16.h>
#include <math.h>

#define BATCH 16
#define CH 512
#define HWN 4096
#define NHEAD 8
#define HD 64
#define BH (BATCH * NHEAD)  // 128

__device__ float g_K[(size_t)BATCH * CH * HWN];
__device__ float g_V[(size_t)BATCH * CH * HWN];
__device__ float g_ctx[BH * HD * HD];          // [bh][d][e]
__device__ float g_P[(size_t)BATCH * CH * CH]; // [b][o][h*64+d]
__device__ float g_G[(size_t)BATCH * CH * CH]; // [b][o][c]
__device__ float g_s[CH];
__device__ float g_s2[CH];
__device__ float g_mean[CH];
__device__ float g_rstd[CH];

// ---------------------------------------------------------------------------
// K0: zero ctx accumulator + BN partial sums.
// ---------------------------------------------------------------------------
__global__ __launch_bounds__(256) void k_zero() {
  const int i = blockIdx.x * 256 + threadIdx.x;
  if (i < BH * HD * HD) g_ctx[i] = 0.f;
  if (i < CH) { g_s[i] = 0.f; g_s2[i] = 0.f; }
}

// ---------------------------------------------------------------------------
// K1: K/V projections, softmax fused into K epilogue.  (proven R9)
// Kc=8, double-buffered stages, one barrier per chunk.
// grid = (32, 8, 16): blockIdx.y -> (which = y>>2, m-tile = y&3)
// ---------------------------------------------------------------------------
__global__ __launch_bounds__(256) void k_gemm_kv(
    const float* __restrict__ x, const float* __restrict__ Wk,
    const float* __restrict__ Wv) {
  const int b = blockIdx.z;
  const int n0 = blockIdx.x * 128;
  const int which = blockIdx.y >> 2;   // 0=K, 1=V
  const int m0 = (blockIdx.y & 3) * 128;
  const float* __restrict__ W = (which == 0) ? Wk : Wv;
  float* Out = (which == 0) ? g_K : g_V;
  const float* __restrict__ Bp = x + (size_t)b * CH * HWN;

  __shared__ float sbuf[4096];

  const int tid = threadIdx.x;
  const int tx = tid & 15, ty = tid >> 4;
  const int arow = tid >> 1, acol = (tid & 1) << 2;
  const int brow = tid >> 5, bcol = (tid & 31) << 2;

  float acc[8][8];
#pragma unroll
  for (int i = 0; i < 8; i++)
#pragma unroll
    for (int j = 0; j < 8; j++) acc[i][j] = 0.f;

  const float* Arow = W + (size_t)(m0 + arow) * CH;

  float4 av = *(const float4*)&Arow[acol];
  float4 bv = *(const float4*)&Bp[(size_t)brow * HWN + n0 + bcol];
  {
    float* As = sbuf;
    float* Bs = sbuf + 1024;
    As[(acol + 0) * 128 + arow] = av.x;
    As[(acol + 1) * 128 + arow] = av.y;
    As[(acol + 2) * 128 + arow] = av.z;
    As[(acol + 3) * 128 + arow] = av.w;
    *(float4*)&Bs[brow * 128 + bcol] = bv;
  }
  __syncthreads();

#pragma unroll 1
  for (int c = 0; c < 64; c++) {
    const int cur = c & 1;
    const bool more = (c + 1) < 64;
    if (more) {
      const int kn = (c + 1) * 8;
      av = *(const float4*)&Arow[kn + acol];
      bv = *(const float4*)&Bp[(size_t)(kn + brow) * HWN + n0 + bcol];
    }
    const float* As = sbuf + cur * 2048;
    const float* Bs = As + 1024;
#pragma unroll
    for (int kk = 0; kk < 8; kk++) {
      float a[8], bb[8];
      *(float4*)&a[0] = *(const float4*)&As[kk * 128 + ty * 8];
      *(float4*)&a[4] = *(const float4*)&As[kk * 128 + ty * 8 + 4];
      *(float4*)&bb[0] = *(const float4*)&Bs[kk * 128 + tx * 8];
      *(float4*)&bb[4] = *(const float4*)&Bs[kk * 128 + tx * 8 + 4];
#pragma unroll
      for (int i = 0; i < 8; i++)
#pragma unroll
        for (int j = 0; j < 8; j++) acc[i][j] += a[i] * bb[j];
    }
    if (more) {
      float* An = sbuf + (cur ^ 1) * 2048;
      float* Bn = An + 1024;
      An[(acol + 0) * 128 + arow] = av.x;
      An[(acol + 1) * 128 + arow] = av.y;
      An[(acol + 2) * 128 + arow] = av.z;
      An[(acol + 3) * 128 + arow] = av.w;
      *(float4*)&Bn[brow * 128 + bcol] = bv;
    }
    __syncthreads();
  }

  if (which == 0) {
    // softmax over d (64 rows/head); rows 0-63 = head A (ty 0-7), 64-127 = B.
    float* red = sbuf;
    const int tb = (ty < 8) ? 0 : 8;
    const int rbase = (ty * 16 + tx) * 8;
    float loc[8];
#pragma unroll
    for (int j = 0; j < 8; j++) {
      float m = acc[0][j];
#pragma unroll
      for (int i = 1; i < 8; i++) m = fmaxf(m, acc[i][j]);
      loc[j] = m;
    }
    *(float4*)&red[rbase] = *(float4*)&loc[0];
    *(float4*)&red[rbase + 4] = *(float4*)&loc[4];
    __syncthreads();
    float gm[8];
#pragma unroll
    for (int j = 0; j < 8; j++) gm[j] = -3.4e38f;
#pragma unroll
    for (int t = 0; t < 8; t++) {
      const int rb = ((tb + t) * 16 + tx) * 8;
      float4 r0 = *(float4*)&red[rb];
      float4 r1 = *(float4*)&red[rb + 4];
      gm[0] = fmaxf(gm[0], r0.x); gm[1] = fmaxf(gm[1], r0.y);
      gm[2] = fmaxf(gm[2], r0.z); gm[3] = fmaxf(gm[3], r0.w);
      gm[4] = fmaxf(gm[4], r1.x); gm[5] = fmaxf(gm[5], r1.y);
      gm[6] = fmaxf(gm[6], r1.z); gm[7] = fmaxf(gm[7], r1.w);
    }
#pragma unroll
    for (int j = 0; j < 8; j++) loc[j] = 0.f;
#pragma unroll
    for (int i = 0; i < 8; i++)
#pragma unroll
      for (int j = 0; j < 8; j++) {
        acc[i][j] = expf(acc[i][j] - gm[j]);
        loc[j] += acc[i][j];
      }
    __syncthreads();
    *(float4*)&red[rbase] = *(float4*)&loc[0];
    *(float4*)&red[rbase + 4] = *(float4*)&loc[4];
    __syncthreads();
    float gs[8];
#pragma unroll
    for (int j = 0; j < 8; j++) gs[j] = 0.f;
#pragma unroll
    for (int t = 0; t < 8; t++) {
      const int rb = ((tb + t) * 16 + tx) * 8;
      float4 r0 = *(float4*)&red[rb];
      float4 r1 = *(float4*)&red[rb + 4];
      gs[0] += r0.x; gs[1] += r0.y; gs[2] += r0.z; gs[3] += r0.w;
      gs[4] += r1.x; gs[5] += r1.y; gs[6] += r1.z; gs[7] += r1.w;
    }
#pragma unroll
    for (int j = 0; j < 8; j++) gs[j] = 1.f / gs[j];
#pragma unroll
    for (int i = 0; i < 8; i++)
#pragma unroll
      for (int j = 0; j < 8; j++) acc[i][j] *= gs[j];
  }

  float* O = Out + ((size_t)b * CH + m0) * HWN + n0;
#pragma unroll
  for (int i = 0; i < 8; i++) {
    float* row = O + (size_t)(ty * 8 + i) * HWN + tx * 8;
    *(float4*)&row[0] = make_float4(acc[i][0], acc[i][1], acc[i][2], acc[i][3]);
    *(float4*)&row[4] = make_float4(acc[i][4], acc[i][5], acc[i][6], acc[i][7]);
  }
}

// ---------------------------------------------------------------------------
// K3: context[bh][d][e] = sum_p K[bh][d][p] * V[bh][e][p]   (proven R7/R9)
// ---------------------------------------------------------------------------
__global__ __launch_bounds__(64) void k_context() {
  const int bh = blockIdx.y;
  const int p0 = blockIdx.x * 512;
  const float* __restrict__ krow =
      g_K + (size_t)bh * HD * HWN + (size_t)threadIdx.x * HWN + p0;
  const float* __restrict__ vrow =
      g_V + (size_t)bh * HD * HWN + (size_t)threadIdx.x * HWN + p0;
  __shared__ __align__(16) float As[16][68];
  __shared__ __align__(16) float Bs[16][68];
  const int tid = threadIdx.x;
  const int tx = tid & 7, ty = tid >> 3;

  float acc[8][8];
#pragma unroll
  for (int i = 0; i < 8; i++)
#pragma unroll
    for (int j = 0; j < 8; j++) acc[i][j] = 0.f;

  float4 kr[4], vr[4];
#pragma unroll
  for (int j = 0; j < 4; j++) {
    kr[j] = *(const float4*)&krow[j * 4];
    vr[j] = *(const float4*)&vrow[j * 4];
  }

  for (int c = 0; c < 32; c++) {
#pragma unroll
    for (int j = 0; j < 4; j++) {
      As[j * 4 + 0][tid] = kr[j].x; As[j * 4 + 1][tid] = kr[j].y;
      As[j * 4 + 2][tid] = kr[j].z; As[j * 4 + 3][tid] = kr[j].w;
      Bs[j * 4 + 0][tid] = vr[j].x; Bs[j * 4 + 1][tid] = vr[j].y;
      Bs[j * 4 + 2][tid] = vr[j].z; Bs[j * 4 + 3][tid] = vr[j].w;
    }
    __syncthreads();
    if (c + 1 < 32) {
      const int pn = (c + 1) * 16;
#pragma unroll
      for (int j = 0; j < 4; j++) {
        kr[j] = *(const float4*)&krow[pn + j * 4];
        vr[j] = *(const float4*)&vrow[pn + j * 4];
      }
    }
#pragma unroll
    for (int kk = 0; kk < 16; kk++) {
      float a[8], bb[8];
      *(float4*)&a[0] = *(float4*)&As[kk][ty * 8];
      *(float4*)&a[4] = *(float4*)&As[kk][ty * 8 + 4];
      *(float4*)&bb[0] = *(float4*)&Bs[kk][tx * 8];
      *(float4*)&bb[4] = *(float4*)&Bs[kk][tx * 8 + 4];
#pragma unroll
      for (int i = 0; i < 8; i++)
#pragma unroll
        for (int j = 0; j < 8; j++) acc[i][j] += a[i] * bb[j];
    }
    __syncthreads();
  }
  float* C = g_ctx + (size_t)bh * HD * HD;
#pragma unroll
  for (int i = 0; i < 8; i++)
#pragma unroll
    for (int j = 0; j < 8; j++)
      atomicAdd(&C[(ty * 8 + i) * HD + tx * 8 + j], acc[i][j]);
}

// ---------------------------------------------------------------------------
// K4: P[b][o][h*64+d] = sum_e Wo[o][h*64+e] * ctx[bh][d][e]
// grid = (4 o-tiles, 128 bh), 256 threads; out tile 128o x 64d.
// ---------------------------------------------------------------------------
__global__ __launch_bounds__(256) void k_P(const float* __restrict__ Wo) {
  const int bh = blockIdx.y;
  const int b = bh >> 3, h = bh & 7;
  const int o0 = blockIdx.x * 128;
  const int tid = threadIdx.x;

  __shared__ float ws[64][129];  // [e][o]  (Wo tile transposed)
  __shared__ float cs[64][65];   // [e][d]  (ctx transposed: cs[e][d] = ctx[d][e])
  const float* C = g_ctx + (size_t)bh * HD * HD;
  // load ctx[d][e] -> cs[e][d]
  for (int i = tid; i < 1024; i += 256) {
    float4 v = ((const float4*)C)[i];   // d = i>>4, e = (i&15)*4
    const int d = i >> 4, e = (i & 15) * 4;
    cs[e + 0][d] = v.x; cs[e + 1][d] = v.y;
    cs[e + 2][d] = v.z; cs[e + 3][d] = v.w;
  }
  // load Wo rows o0..o0+127, cols h*64..h*64+63 -> ws[e][o]
  for (int i = tid; i < 2048; i += 256) {
    const int o = i >> 4, e = (i & 15) * 4;
    float4 v = *(const float4*)&Wo[(size_t)(o0 + o) * CH + h * 64 + e];
    ws[e + 0][o] = v.x; ws[e + 1][o] = v.y;
    ws[e + 2][o] = v.z; ws[e + 3][o] = v.w;
  }
  __syncthreads();

  const int tx = tid & 15, ty = tid >> 4;   // tx: d (4 each), ty: o (8 each)
  float acc[8][4];
#pragma unroll
  for (int i = 0; i < 8; i++)
#pragma unroll
    for (int j = 0; j < 4; j++) acc[i][j] = 0.f;

  for (int e = 0; e < 64; e++) {
    float w[8], a[4];
#pragma unroll
    for (int i = 0; i < 8; i++) w[i] = ws[e][ty * 8 + i];
#pragma unroll
    for (int j = 0; j < 4; j++) a[j] = cs[e][tx * 4 + j];
#pragma unroll
    for (int i = 0; i < 8; i++)
#pragma unroll
      for (int j = 0; j < 4; j++) acc[i][j] += w[i] * a[j];
  }
#pragma unroll
  for (int i = 0; i < 8; i++)
#pragma unroll
    for (int j = 0; j < 4; j++)
      g_P[((size_t)b * CH + o0 + ty * 8 + i) * CH + h * 64 + tx * 4 + j] =
          acc[i][j];
}

// ---------------------------------------------------------------------------
// K5: G[b][o][c] = sum_hd P[b][o][hd] * Wq[hd][c]
// (proven k_gk tile; A = per-batch P, B = Wq)  grid = (4, 4, 16).
// ---------------------------------------------------------------------------
__global__ __launch_bounds__(256) void k_gk(const float* __restrict__ Wq) {
  const int b = blockIdx.z;
  const int n0 = blockIdx.x * 128;
  const int m0 = blockIdx.y * 128;
  const float* __restrict__ Ap = g_P + (size_t)b * CH * CH;

  __shared__ float As[8][128];
  __shared__ float Bs[8][128];
  const int tid = threadIdx.x;
  const int tx = tid & 15, ty = tid >> 4;
  const int arow = tid >> 1, acol = (tid & 1) << 2;
  const int brow = tid >> 5, bcol = (tid & 31) << 2;

  float acc[8][8];
#pragma unroll
  for (int i = 0; i < 8; i++)
#pragma unroll
    for (int j = 0; j < 8; j++) acc[i][j] = 0.f;

  for (int k0 = 0; k0 < CH; k0 += 8) {
    float4 av = *(const float4*)&Ap[(size_t)(m0 + arow) * CH + k0 + acol];
    As[acol + 0][arow] = av.x;
    As[acol + 1][arow] = av.y;
    As[acol + 2][arow] = av.z;
    As[acol + 3][arow] = av.w;
    *(float4*)&Bs[brow][bcol] =
        *(const float4*)&Wq[(size_t)(k0 + brow) * CH + n0 + bcol];
    __syncthreads();
#pragma unroll
    for (int kk = 0; kk < 8; kk++) {
      float a[8], bb[8];
      *(float4*)&a[0] = *(float4*)&As[kk][ty * 8];
      *(float4*)&a[4] = *(float4*)&As[kk][ty * 8 + 4];
      *(float4*)&bb[0] = *(float4*)&Bs[kk][tx * 8];
      *(float4*)&bb[4] = *(float4*)&Bs[kk][tx * 8 + 4];
#pragma unroll
      for (int i = 0; i < 8; i++)
#pragma unroll
        for (int j = 0; j < 8; j++) acc[i][j] += a[i] * bb[j];
    }
    __syncthreads();
  }
  float* O = g_G + ((size_t)b * CH + m0) * CH + n0;
#pragma unroll
  for (int i = 0; i < 8; i++) {
    float* row = O + (size_t)(ty * 8 + i) * CH + tx * 8;
    *(float4*)&row[0] = make_float4(acc[i][0], acc[i][1], acc[i][2], acc[i][3]);
    *(float4*)&row[4] = make_float4(acc[i][4], acc[i][5], acc[i][6], acc[i][7]);
  }
}

// ---------------------------------------------------------------------------
// K6: y = G_b @ x + x, BN stats fused.  (proven R7/R9 version)
// ---------------------------------------------------------------------------
__global__ __launch_bounds__(256) void k_final(const float* __restrict__ x,
                                               float* __restrict__ y) {
  const int b = blockIdx.z;
  const int n0 = blockIdx.x * 128;
  const int m0 = blockIdx.y * 128;
  const float* __restrict__ A = g_G + (size_t)b * CH * CH;
  const float* __restrict__ Bp = x + (size_t)b * CH * HWN;

  __shared__ float As[8][128];
  __shared__ float Bs[8][128];
  const int tid = threadIdx.x;
  const int tx = tid & 15, ty = tid >> 4;
  const int arow = tid >> 1, acol = (tid & 1) << 2;
  const int brow = tid >> 5, bcol = (tid & 31) << 2;

  float acc[8][8];
#pragma unroll
  for (int i = 0; i < 8; i++)
#pragma unroll
    for (int j = 0; j < 8; j++) acc[i][j] = 0.f;

  float4 av = *(const float4*)&A[(size_t)(m0 + arow) * CH + acol];
  float4 bv = *(const float4*)&Bp[(size_t)brow * HWN + n0 + bcol];

  for (int k0 = 0; k0 < CH; k0 += 8) {
    As[acol + 0][arow] = av.x;
    As[acol + 1][arow] = av.y;
    As[acol + 2][arow] = av.z;
    As[acol + 3][arow] = av.w;
    *(float4*)&Bs[brow][bcol] = bv;
    __syncthreads();
    if (k0 + 8 < CH) {
      av = *(const float4*)&A[(size_t)(m0 + arow) * CH + k0 + 8 + acol];
      bv = *(const float4*)&Bp[(size_t)(k0 + 8 + brow) * HWN + n0 + bcol];
    }
#pragma unroll
    for (int kk = 0; kk < 8; kk++) {
      float a[8], bb[8];
      *(float4*)&a[0] = *(float4*)&As[kk][ty * 8];
      *(float4*)&a[4] = *(float4*)&As[kk][ty * 8 + 4];
      *(float4*)&bb[0] = *(float4*)&Bs[kk][tx * 8];
      *(float4*)&bb[4] = *(float4*)&Bs[kk][tx * 8 + 4];
#pragma unroll
      for (int i = 0; i < 8; i++)
#pragma unroll
        for (int j = 0; j < 8; j++) acc[i][j] += a[i] * bb[j];
    }
    __syncthreads();
  }

#pragma unroll
  for (int i = 0; i < 8; i++) {
    const size_t base = ((size_t)b * CH + m0 + ty * 8 + i) * HWN + n0 + tx * 8;
    float4 x0 = *(const float4*)&x[base];
    float4 x1 = *(const float4*)&x[base + 4];
    acc[i][0] += x0.x; acc[i][1] += x0.y; acc[i][2] += x0.z; acc[i][3] += x0.w;
    acc[i][4] += x1.x; acc[i][5] += x1.y; acc[i][6] += x1.z; acc[i][7] += x1.w;
    *(float4*)&y[base] = make_float4(acc[i][0], acc[i][1], acc[i][2], acc[i][3]);
    *(float4*)&y[base + 4] =
        make_float4(acc[i][4], acc[i][5], acc[i][6], acc[i][7]);
  }

#pragma unroll
  for (int i = 0; i < 8; i++) {
    float s = 0.f, s2 = 0.f;
#pragma unroll
    for (int j = 0; j < 8; j++) {
      s += acc[i][j];
      s2 += acc[i][j] * acc[i][j];
    }
#pragma unroll
    for (int d = 8; d > 0; d >>= 1) {
      s += __shfl_down_sync(0xffffffffu, s, d, 16);
      s2 += __shfl_down_sync(0xffffffffu, s2, d, 16);
    }
    if (tx == 0) {
      const int ch = m0 + ty * 8 + i;
      atomicAdd(&g_s[ch], s);
      atomicAdd(&g_s2[ch], s2);
    }
  }
}

// ---------------------------------------------------------------------------
// K7: finalize BN stats.  one block, 512 threads.
// ---------------------------------------------------------------------------
__global__ void k_bn_finalize() {
  const int c = threadIdx.x;
  const float inv_n = 1.f / (float)(BATCH * HWN);
  const float mean = g_s[c] * inv_n;
  const float var = g_s2[c] * inv_n - mean * mean;
  g_mean[c] = mean;
  g_rstd[c] = rsqrtf(var + 1e-5f);
}

// ---------------------------------------------------------------------------
// K8: normalize in place + affine.
// ---------------------------------------------------------------------------
__global__ __launch_bounds__(256) void k_bn_apply(float* __restrict__ y,
                                                  const float* __restrict__ gamma,
                                                  const float* __restrict__ beta) {
  const size_t i4 = (size_t)blockIdx.x * 256 + threadIdx.x;
  const int c = (int)((i4 >> 10) & (CH - 1));
  float4 v = ((const float4*)y)[i4];
  const float mu = g_mean[c];
  const float sc = g_rstd[c] * gamma[c];
  const float bt = beta[c];
  v.x = (v.x - mu) * sc + bt;
  v.y = (v.y - mu) * sc + bt;
  v.z = (v.z - mu) * sc + bt;
  v.w = (v.w - mu) * sc + bt;
  ((float4*)y)[i4] = v;
}

// ---------------------------------------------------------------------------
extern "C" void kernel_launch(void* const* d_in, const int* in_sizes, int n_in,
                              void* d_out, int out_size) {
  const float* x = (const float*)d_in[0];
  const float* Wq = (const float*)d_in[1];
  const float* Wk = (const float*)d_in[2];
  const float* Wv = (const float*)d_in[3];
  const float* Wo = (const float*)d_in[4];
  const float* gamma = (const float*)d_in[5];
  const float* beta = (const float*)d_in[6];
  float* y = (float*)d_out;

  k_zero<<<2048, 256>>>();
  k_gemm_kv<<<dim3(32, 8, 16), 256>>>(x, Wk, Wv);
  k_context<<<dim3(8, 128), 64>>>();
  k_P<<<dim3(4, 128), 256>>>(Wo);
  k_gk<<<dim3(4, 4, 16), 256>>>(Wq);
  k_final<<<dim3(32, 4, 16), 256>>>(x, y);
  k_bn_finalize<<<1, 512>>>();
  k_bn_apply<<<32768, 256>>>(y, gamma, beta);
}

// round 15
// speedup vs baseline: 1.0495x; 1.0027x over previous
#include <cuda_runtime.h>
#include <cuda_bf16.h>
#include <math.h>

#define BATCH 16
#define CH 512
#define HWN 4096
#define NHEAD 8
#define HD 64
#define BH (BATCH * NHEAD)  // 128
#define CSPLIT 16
#define CPCHUNK (HWN / CSPLIT)  // 256

__device__ float g_K[(size_t)BATCH * CH * HWN];
__device__ float g_V[(size_t)BATCH * CH * HWN];
__device__ float g_ctx[BH * HD * HD];          // [bh][d][e]
__device__ float g_P[(size_t)BATCH * CH * CH]; // [b][o][h*64+d]
__device__ float g_G[(size_t)BATCH * CH * CH]; // [b][o][c]
__device__ float g_s[CH];
__device__ float g_s2[CH];
__device__ float g_mean[CH];
__device__ float g_rstd[CH];

// ---------------------------------------------------------------------------
// K0: zero ctx accumulator + BN partial sums.
// ---------------------------------------------------------------------------
__global__ __launch_bounds__(256) void k_zero() {
  const int i = blockIdx.x * 256 + threadIdx.x;
  if (i < BH * HD * HD) g_ctx[i] = 0.f;
  if (i < CH) { g_s[i] = 0.f; g_s2[i] = 0.f; }
}

// ---------------------------------------------------------------------------
// K1: K/V projections, softmax fused into K epilogue.  (proven R9/R14)
// Kc=8, double-buffered stages, one barrier per chunk.
// grid = (32, 8, 16): blockIdx.y -> (which = y>>2, m-tile = y&3)
// ---------------------------------------------------------------------------
__global__ __launch_bounds__(256) void k_gemm_kv(
    const float* __restrict__ x, const float* __restrict__ Wk,
    const float* __restrict__ Wv) {
  const int b = blockIdx.z;
  const int n0 = blockIdx.x * 128;
  const int which = blockIdx.y >> 2;   // 0=K, 1=V
  const int m0 = (blockIdx.y & 3) * 128;
  const float* __restrict__ W = (which == 0) ? Wk : Wv;
  float* Out = (which == 0) ? g_K : g_V;
  const float* __restrict__ Bp = x + (size_t)b * CH * HWN;

  __shared__ float sbuf[4096];

  const int tid = threadIdx.x;
  const int tx = tid & 15, ty = tid >> 4;
  const int arow = tid >> 1, acol = (tid & 1) << 2;
  const int brow = tid >> 5, bcol = (tid & 31) << 2;

  float acc[8][8];
#pragma unroll
  for (int i = 0; i < 8; i++)
#pragma unroll
    for (int j = 0; j < 8; j++) acc[i][j] = 0.f;

  const float* Arow = W + (size_t)(m0 + arow) * CH;

  float4 av = *(const float4*)&Arow[acol];
  float4 bv = *(const float4*)&Bp[(size_t)brow * HWN + n0 + bcol];
  {
    float* As = sbuf;
    float* Bs = sbuf + 1024;
    As[(acol + 0) * 128 + arow] = av.x;
    As[(acol + 1) * 128 + arow] = av.y;
    As[(acol + 2) * 128 + arow] = av.z;
    As[(acol + 3) * 128 + arow] = av.w;
    *(float4*)&Bs[brow * 128 + bcol] = bv;
  }
  __syncthreads();

#pragma unroll 1
  for (int c = 0; c < 64; c++) {
    const int cur = c & 1;
    const bool more = (c + 1) < 64;
    if (more) {
      const int kn = (c + 1) * 8;
      av = *(const float4*)&Arow[kn + acol];
      bv = *(const float4*)&Bp[(size_t)(kn + brow) * HWN + n0 + bcol];
    }
    const float* As = sbuf + cur * 2048;
    const float* Bs = As + 1024;
#pragma unroll
    for (int kk = 0; kk < 8; kk++) {
      float a[8], bb[8];
      *(float4*)&a[0] = *(const float4*)&As[kk * 128 + ty * 8];
      *(float4*)&a[4] = *(const float4*)&As[kk * 128 + ty * 8 + 4];
      *(float4*)&bb[0] = *(const float4*)&Bs[kk * 128 + tx * 8];
      *(float4*)&bb[4] = *(const float4*)&Bs[kk * 128 + tx * 8 + 4];
#pragma unroll
      for (int i = 0; i < 8; i++)
#pragma unroll
        for (int j = 0; j < 8; j++) acc[i][j] += a[i] * bb[j];
    }
    if (more) {
      float* An = sbuf + (cur ^ 1) * 2048;
      float* Bn = An + 1024;
      An[(acol + 0) * 128 + arow] = av.x;
      An[(acol + 1) * 128 + arow] = av.y;
      An[(acol + 2) * 128 + arow] = av.z;
      An[(acol + 3) * 128 + arow] = av.w;
      *(float4*)&Bn[brow * 128 + bcol] = bv;
    }
    __syncthreads();
  }

  if (which == 0) {
    // softmax over d (64 rows/head); rows 0-63 = head A (ty 0-7), 64-127 = B.
    float* red = sbuf;
    const int tb = (ty < 8) ? 0 : 8;
    const int rbase = (ty * 16 + tx) * 8;
    float loc[8];
#pragma unroll
    for (int j = 0; j < 8; j++) {
      float m = acc[0][j];
#pragma unroll
      for (int i = 1; i < 8; i++) m = fmaxf(m, acc[i][j]);
      loc[j] = m;
    }
    *(float4*)&red[rbase] = *(float4*)&loc[0];
    *(float4*)&red[rbase + 4] = *(float4*)&loc[4];
    __syncthreads();
    float gm[8];
#pragma unroll
    for (int j = 0; j < 8; j++) gm[j] = -3.4e38f;
#pragma unroll
    for (int t = 0; t < 8; t++) {
      const int rb = ((tb + t) * 16 + tx) * 8;
      float4 r0 = *(float4*)&red[rb];
      float4 r1 = *(float4*)&red[rb + 4];
      gm[0] = fmaxf(gm[0], r0.x); gm[1] = fmaxf(gm[1], r0.y);
      gm[2] = fmaxf(gm[2], r0.z); gm[3] = fmaxf(gm[3], r0.w);
      gm[4] = fmaxf(gm[4], r1.x); gm[5] = fmaxf(gm[5], r1.y);
      gm[6] = fmaxf(gm[6], r1.z); gm[7] = fmaxf(gm[7], r1.w);
    }
#pragma unroll
    for (int j = 0; j < 8; j++) loc[j] = 0.f;
#pragma unroll
    for (int i = 0; i < 8; i++)
#pragma unroll
      for (int j = 0; j < 8; j++) {
        acc[i][j] = expf(acc[i][j] - gm[j]);
        loc[j] += acc[i][j];
      }
    __syncthreads();
    *(float4*)&red[rbase] = *(float4*)&loc[0];
    *(float4*)&red[rbase + 4] = *(float4*)&loc[4];
    __syncthreads();
    float gs[8];
#pragma unroll
    for (int j = 0; j < 8; j++) gs[j] = 0.f;
#pragma unroll
    for (int t = 0; t < 8; t++) {
      const int rb = ((tb + t) * 16 + tx) * 8;
      float4 r0 = *(float4*)&red[rb];
      float4 r1 = *(float4*)&red[rb + 4];
      gs[0] += r0.x; gs[1] += r0.y; gs[2] += r0.z; gs[3] += r0.w;
      gs[4] += r1.x; gs[5] += r1.y; gs[6] += r1.z; gs[7] += r1.w;
    }
#pragma unroll
    for (int j = 0; j < 8; j++) gs[j] = 1.f / gs[j];
#pragma unroll
    for (int i = 0; i < 8; i++)
#pragma unroll
      for (int j = 0; j < 8; j++) acc[i][j] *= gs[j];
  }

  float* O = Out + ((size_t)b * CH + m0) * HWN + n0;
#pragma unroll
  for (int i = 0; i < 8; i++) {
    float* row = O + (size_t)(ty * 8 + i) * HWN + tx * 8;
    *(float4*)&row[0] = make_float4(acc[i][0], acc[i][1], acc[i][2], acc[i][3]);
    *(float4*)&row[4] = make_float4(acc[i][4], acc[i][5], acc[i][6], acc[i][7]);
  }
}

// ---------------------------------------------------------------------------
// K3: context[bh][d][e] = sum_p K[bh][d][p] * V[bh][e][p]
// 16-way p-split (grid 2048) for deeper co-residency; 64 threads, 8x8 tile.
// ---------------------------------------------------------------------------
__global__ __launch_bounds__(64) void k_context() {
  const int bh = blockIdx.y;
  const int p0 = blockIdx.x * CPCHUNK;
  const float* __restrict__ krow =
      g_K + (size_t)bh * HD * HWN + (size_t)threadIdx.x * HWN + p0;
  const float* __restrict__ vrow =
      g_V + (size_t)bh * HD * HWN + (size_t)threadIdx.x * HWN + p0;
  __shared__ __align__(16) float As[16][68];
  __shared__ __align__(16) float Bs[16][68];
  const int tid = threadIdx.x;
  const int tx = tid & 7, ty = tid >> 3;

  float acc[8][8];
#pragma unroll
  for (int i = 0; i < 8; i++)
#pragma unroll
    for (int j = 0; j < 8; j++) acc[i][j] = 0.f;

  float4 kr[4], vr[4];
#pragma unroll
  for (int j = 0; j < 4; j++) {
    kr[j] = *(const float4*)&krow[j * 4];
    vr[j] = *(const float4*)&vrow[j * 4];
  }

  for (int c = 0; c < CPCHUNK / 16; c++) {
#pragma unroll
    for (int j = 0; j < 4; j++) {
      As[j * 4 + 0][tid] = kr[j].x; As[j * 4 + 1][tid] = kr[j].y;
      As[j * 4 + 2][tid] = kr[j].z; As[j * 4 + 3][tid] = kr[j].w;
      Bs[j * 4 + 0][tid] = vr[j].x; Bs[j * 4 + 1][tid] = vr[j].y;
      Bs[j * 4 + 2][tid] = vr[j].z; Bs[j * 4 + 3][tid] = vr[j].w;
    }
    __syncthreads();
    if (c + 1 < CPCHUNK / 16) {
      const int pn = (c + 1) * 16;
#pragma unroll
      for (int j = 0; j < 4; j++) {
        kr[j] = *(const float4*)&krow[pn + j * 4];
        vr[j] = *(const float4*)&vrow[pn + j * 4];
      }
    }
#pragma unroll
    for (int kk = 0; kk < 16; kk++) {
      float a[8], bb[8];
      *(float4*)&a[0] = *(float4*)&As[kk][ty * 8];
      *(float4*)&a[4] = *(float4*)&As[kk][ty * 8 + 4];
      *(float4*)&bb[0] = *(float4*)&Bs[kk][tx * 8];
      *(float4*)&bb[4] = *(float4*)&Bs[kk][tx * 8 + 4];
#pragma unroll
      for (int i = 0; i < 8; i++)
#pragma unroll
        for (int j = 0; j < 8; j++) acc[i][j] += a[i] * bb[j];
    }
    __syncthreads();
  }
  float* C = g_ctx + (size_t)bh * HD * HD;
#pragma unroll
  for (int i = 0; i < 8; i++)
#pragma unroll
    for (int j = 0; j < 8; j++)
      atomicAdd(&C[(ty * 8 + i) * HD + tx * 8 + j], acc[i][j]);
}

// ---------------------------------------------------------------------------
// K4: P[b][o][h*64+d] = sum_e Wo[o][h*64+e] * ctx[bh][d][e]   (proven R14)
// grid = (4 o-tiles, 128 bh), 256 threads; out tile 128o x 64d.
// ---------------------------------------------------------------------------
__global__ __launch_bounds__(256) void k_P(const float* __restrict__ Wo) {
  const int bh = blockIdx.y;
  const int b = bh >> 3, h = bh & 7;
  const int o0 = blockIdx.x * 128;
  const int tid = threadIdx.x;

  __shared__ float ws[64][129];  // [e][o]
  __shared__ float cs[64][65];   // [e][d]
  const float* C = g_ctx + (size_t)bh * HD * HD;
  for (int i = tid; i < 1024; i += 256) {
    float4 v = ((const float4*)C)[i];
    const int d = i >> 4, e = (i & 15) * 4;
    cs[e + 0][d] = v.x; cs[e + 1][d] = v.y;
    cs[e + 2][d] = v.z; cs[e + 3][d] = v.w;
  }
  for (int i = tid; i < 2048; i += 256) {
    const int o = i >> 4, e = (i & 15) * 4;
    float4 v = *(const float4*)&Wo[(size_t)(o0 + o) * CH + h * 64 + e];
    ws[e + 0][o] = v.x; ws[e + 1][o] = v.y;
    ws[e + 2][o] = v.z; ws[e + 3][o] = v.w;
  }
  __syncthreads();

  const int tx = tid & 15, ty = tid >> 4;
  float acc[8][4];
#pragma unroll
  for (int i = 0; i < 8; i++)
#pragma unroll
    for (int j = 0; j < 4; j++) acc[i][j] = 0.f;

  for (int e = 0; e < 64; e++) {
    float w[8], a[4];
#pragma unroll
    for (int i = 0; i < 8; i++) w[i] = ws[e][ty * 8 + i];
#pragma unroll
    for (int j = 0; j < 4; j++) a[j] = cs[e][tx * 4 + j];
#pragma unroll
    for (int i = 0; i < 8; i++)
#pragma unroll
      for (int j = 0; j < 4; j++) acc[i][j] += w[i] * a[j];
  }
#pragma unroll
  for (int i = 0; i < 8; i++)
#pragma unroll
    for (int j = 0; j < 4; j++)
      g_P[((size_t)b * CH + o0 + ty * 8 + i) * CH + h * 64 + tx * 4 + j] =
          acc[i][j];
}

// ---------------------------------------------------------------------------
// K5: G[b][o][c] = sum_hd P[b][o][hd] * Wq[hd][c]   (proven R14)
// ---------------------------------------------------------------------------
__global__ __launch_bounds__(256) void k_gk(const float* __restrict__ Wq) {
  const int b = blockIdx.z;
  const int n0 = blockIdx.x * 128;
  const int m0 = blockIdx.y * 128;
  const float* __restrict__ Ap = g_P + (size_t)b * CH * CH;

  __shared__ float As[8][128];
  __shared__ float Bs[8][128];
  const int tid = threadIdx.x;
  const int tx = tid & 15, ty = tid >> 4;
  const int arow = tid >> 1, acol = (tid & 1) << 2;
  const int brow = tid >> 5, bcol = (tid & 31) << 2;

  float acc[8][8];
#pragma unroll
  for (int i = 0; i < 8; i++)
#pragma unroll
    for (int j = 0; j < 8; j++) acc[i][j] = 0.f;

  for (int k0 = 0; k0 < CH; k0 += 8) {
    float4 av = *(const float4*)&Ap[(size_t)(m0 + arow) * CH + k0 + acol];
    As[acol + 0][arow] = av.x;
    As[acol + 1][arow] = av.y;
    As[acol + 2][arow] = av.z;
    As[acol + 3][arow] = av.w;
    *(float4*)&Bs[brow][bcol] =
        *(const float4*)&Wq[(size_t)(k0 + brow) * CH + n0 + bcol];
    __syncthreads();
#pragma unroll
    for (int kk = 0; kk < 8; kk++) {
      float a[8], bb[8];
      *(float4*)&a[0] = *(float4*)&As[kk][ty * 8];
      *(float4*)&a[4] = *(float4*)&As[kk][ty * 8 + 4];
      *(float4*)&bb[0] = *(float4*)&Bs[kk][tx * 8];
      *(float4*)&bb[4] = *(float4*)&Bs[kk][tx * 8 + 4];
#pragma unroll
      for (int i = 0; i < 8; i++)
#pragma unroll
        for (int j = 0; j < 8; j++) acc[i][j] += a[i] * bb[j];
    }
    __syncthreads();
  }
  float* O = g_G + ((size_t)b * CH + m0) * CH + n0;
#pragma unroll
  for (int i = 0; i < 8; i++) {
    float* row = O + (size_t)(ty * 8 + i) * CH + tx * 8;
    *(float4*)&row[0] = make_float4(acc[i][0], acc[i][1], acc[i][2], acc[i][3]);
    *(float4*)&row[4] = make_float4(acc[i][4], acc[i][5], acc[i][6], acc[i][7]);
  }
}

// ---------------------------------------------------------------------------
// K6: y = G_b @ x + x, BN stats fused.  (proven R7/R9/R14 version)
// ---------------------------------------------------------------------------
__global__ __launch_bounds__(256) void k_final(const float* __restrict__ x,
                                               float* __restrict__ y) {
  const int b = blockIdx.z;
  const int n0 = blockIdx.x * 128;
  const int m0 = blockIdx.y * 128;
  const float* __restrict__ A = g_G + (size_t)b * CH * CH;
  const float* __restrict__ Bp = x + (size_t)b * CH * HWN;

  __shared__ float As[8][128];
  __shared__ float Bs[8][128];
  const int tid = threadIdx.x;
  const int tx = tid & 15, ty = tid >> 4;
  const int arow = tid >> 1, acol = (tid & 1) << 2;
  const int brow = tid >> 5, bcol = (tid & 31) << 2;

  float acc[8][8];
#pragma unroll
  for (int i = 0; i < 8; i++)
#pragma unroll
    for (int j = 0; j < 8; j++) acc[i][j] = 0.f;

  float4 av = *(const float4*)&A[(size_t)(m0 + arow) * CH + acol];
  float4 bv = *(const float4*)&Bp[(size_t)brow * HWN + n0 + bcol];

  for (int k0 = 0; k0 < CH; k0 += 8) {
    As[acol + 0][arow] = av.x;
    As[acol + 1][arow] = av.y;
    As[acol + 2][arow] = av.z;
    As[acol + 3][arow] = av.w;
    *(float4*)&Bs[brow][bcol] = bv;
    __syncthreads();
    if (k0 + 8 < CH) {
      av = *(const float4*)&A[(size_t)(m0 + arow) * CH + k0 + 8 + acol];
      bv = *(const float4*)&Bp[(size_t)(k0 + 8 + brow) * HWN + n0 + bcol];
    }
#pragma unroll
    for (int kk = 0; kk < 8; kk++) {
      float a[8], bb[8];
      *(float4*)&a[0] = *(float4*)&As[kk][ty * 8];
      *(float4*)&a[4] = *(float4*)&As[kk][ty * 8 + 4];
      *(float4*)&bb[0] = *(float4*)&Bs[kk][tx * 8];
      *(float4*)&bb[4] = *(float4*)&Bs[kk][tx * 8 + 4];
#pragma unroll
      for (int i = 0; i < 8; i++)
#pragma unroll
        for (int j = 0; j < 8; j++) acc[i][j] += a[i] * bb[j];
    }
    __syncthreads();
  }

#pragma unroll
  for (int i = 0; i < 8; i++) {
    const size_t base = ((size_t)b * CH + m0 + ty * 8 + i) * HWN + n0 + tx * 8;
    float4 x0 = *(const float4*)&x[base];
    float4 x1 = *(const float4*)&x[base + 4];
    acc[i][0] += x0.x; acc[i][1] += x0.y; acc[i][2] += x0.z; acc[i][3] += x0.w;
    acc[i][4] += x1.x; acc[i][5] += x1.y; acc[i][6] += x1.z; acc[i][7] += x1.w;
    *(float4*)&y[base] = make_float4(acc[i][0], acc[i][1], acc[i][2], acc[i][3]);
    *(float4*)&y[base + 4] =
        make_float4(acc[i][4], acc[i][5], acc[i][6], acc[i][7]);
  }

#pragma unroll
  for (int i = 0; i < 8; i++) {
    float s = 0.f, s2 = 0.f;
#pragma unroll
    for (int j = 0; j < 8; j++) {
      s += acc[i][j];
      s2 += acc[i][j] * acc[i][j];
    }
#pragma unroll
    for (int d = 8; d > 0; d >>= 1) {
      s += __shfl_down_sync(0xffffffffu, s, d, 16);
      s2 += __shfl_down_sync(0xffffffffu, s2, d, 16);
    }
    if (tx == 0) {
      const int ch = m0 + ty * 8 + i;
      atomicAdd(&g_s[ch], s);
      atomicAdd(&g_s2[ch], s2);
    }
  }
}

// ---------------------------------------------------------------------------
// K7: finalize BN stats.  one block, 512 threads.
// ---------------------------------------------------------------------------
__global__ void k_bn_finalize() {
  const int c = threadIdx.x;
  const float inv_n = 1.f / (float)(BATCH * HWN);
  const float mean = g_s[c] * inv_n;
  const float var = g_s2[c] * inv_n - mean * mean;
  g_mean[c] = mean;
  g_rstd[c] = rsqrtf(var + 1e-5f);
}

// ---------------------------------------------------------------------------
// K8: normalize in place + affine.
// ---------------------------------------------------------------------------
__global__ __launch_bounds__(256) void k_bn_apply(float* __restrict__ y,
                                                  const float* __restrict__ gamma,
                                                  const float* __restrict__ beta) {
  const size_t i4 = (size_t)blockIdx.x * 256 + threadIdx.x;
  const int c = (int)((i4 >> 10) & (CH - 1));
  float4 v = ((const float4*)y)[i4];
  const float mu = g_mean[c];
  const float sc = g_rstd[c] * gamma[c];
  const float bt = beta[c];
  v.x = (v.x - mu) * sc + bt;
  v.y = (v.y - mu) * sc + bt;
  v.z = (v.z - mu) * sc + bt;
  v.w = (v.w - mu) * sc + bt;
  ((float4*)y)[i4] = v;
}

// ---------------------------------------------------------------------------
extern "C" void kernel_launch(void* const* d_in, const int* in_sizes, int n_in,
                              void* d_out, int out_size) {
  const float* x = (const float*)d_in[0];
  const float* Wq = (const float*)d_in[1];
  const float* Wk = (const float*)d_in[2];
  const float* Wv = (const float*)d_in[3];
  const float* Wo = (const float*)d_in[4];
  const float* gamma = (const float*)d_in[5];
  const float* beta = (const float*)d_in[6];
  float* y = (float*)d_out;

  k_zero<<<2048, 256>>>();
  k_gemm_kv<<<dim3(32, 8, 16), 256>>>(x, Wk, Wv);
  k_context<<<dim3(CSPLIT, BH), 64>>>();
  k_P<<<dim3(4, 128), 256>>>(Wo);
  k_gk<<<dim3(4, 4, 16), 256>>>(Wq);
  k_final<<<dim3(32, 4, 16), 256>>>(x, y);
  k_bn_finalize<<<1, 512>>>();
  k_bn_apply<<<32768, 256>>>(y, gamma, beta);
}